// round 16
// baseline (speedup 1.0000x reference)
#include <cuda_runtime.h>
#include <math.h>

#define KC 192
#define Q_MIN 0.5f
#define TPB1 256
#define TPB3 256
#define GS 8
#define NCELL (GS * GS * GS)   // 512 cells over [-4,4]^3, cell size 1.0
#define CAP 151552             // max points supported by sort buffers (>= n)

// ---------------- device scratch (no allocations allowed) ----------------
__device__ unsigned long long g_key[KC * 128];   // 1024B-strided per-cluster argmax
__device__ float2 g_wsp[KC * 128];               // {wsum, w*(el+pl)}
__device__ float g_nacc[32 * 256];

// scalar cluster table
__device__ float4 g_B4[KC];    // {Bx, By, Bz, Bw}  (B = -2a, Bw = |a|^2)
__device__ float  g_q[KC];     // q_alpha (0 if cluster empty)
__device__ float  g_qsum;

// counting-sort scratch
__device__ int g_ccnt[NCELL];
__device__ int g_cbase[NCELL];
__device__ unsigned g_prank[CAP];   // (cell<<23)|rank
__device__ int g_order[CAP];

// 0 att, 1 rep, 2 minb, 3 pay, 4 noise_sum, 5 noise_cnt, 6 nobj
__device__ float g_s[8];
__device__ unsigned g_done1, g_done2;

// ---------------- helpers ----------------
__device__ __forceinline__ float warp_sum(float v) {
    #pragma unroll
    for (int o = 16; o > 0; o >>= 1) v += __shfl_down_sync(0xFFFFFFFFu, v, o);
    return v;
}
__device__ __forceinline__ float warp_max(float v) {
    #pragma unroll
    for (int o = 16; o > 0; o >>= 1) v = fmaxf(v, __shfl_down_sync(0xFFFFFFFFu, v, o));
    return v;
}
__device__ __forceinline__ float clip_beta(float b) {
    return fminf(fmaxf(b, 1e-4f), 1.0f - 1e-4f);
}
__device__ __forceinline__ float fsqrt_ap(float x) {
    float r; asm("sqrt.approx.f32 %0, %1;" : "=f"(r) : "f"(x)); return r;
}
__device__ __forceinline__ void red_add_v2(float2* addr, float a, float b) {
    asm volatile("red.global.add.v2.f32 [%0], {%1, %2};" :: "l"(addr), "f"(a), "f"(b) : "memory");
}
__device__ __forceinline__ int cell_of(float x, float y, float z) {
    int cx = min(GS - 1, max(0, (int)floorf(x + 4.0f)));
    int cy = min(GS - 1, max(0, (int)floorf(y + 4.0f)));
    int cz = min(GS - 1, max(0, (int)floorf(z + 4.0f)));
    return cx + GS * cy + GS * GS * cz;
}

// ---------------- pass 1: per-point reductions + cell binning + fused cluster stage ----------------
__global__ void __launch_bounds__(TPB1) k_pass1(const float* __restrict__ pbeta,
                        const float* __restrict__ tenergy,
                        const float* __restrict__ penergy,
                        const float* __restrict__ tpos,
                        const float* __restrict__ ppos,
                        const int*   __restrict__ tidx,
                        const float* __restrict__ cc,
                        const float* __restrict__ ttime,
                        int n)
{
    int t = threadIdx.x;
    int i = blockIdx.x * TPB1 + t;
    float nsum = 0.0f, ncnt = 0.0f;
    if (i < n) {
        float b = clip_beta(pbeta[i]);
        int k = tidx[i];

        // cell binning for the spatial sort (all points)
        float x0 = cc[3 * i], x1 = cc[3 * i + 1], x2 = cc[3 * i + 2];
        int c = cell_of(x0, x1, x2);
        unsigned r = (unsigned)atomicAdd(&g_ccnt[c], 1);
        g_prank[i] = ((unsigned)c << 23) | (r & 0x7FFFFFu);

        if (k >= 0) {
            float a = atanhf(b);
            float w = a * a;
            unsigned long long key =
                ((unsigned long long)__float_as_uint(b) << 32) |
                (unsigned long long)(0xFFFFFFFFu - (unsigned)i);
            atomicMax(&g_key[k * 128], key);

            float te = tenergy[i], pe = penergy[i];
            float de = te - pe;
            float el = (de * de) / (te * te);

            float2 tp = ((const float2*)tpos)[i];
            float2 pp = ((const float2*)ppos)[i];
            float d0 = tp.x - pp.x, d1 = tp.y - pp.y;
            float pl = (d0 * d0) / (tp.x * tp.x) + (d1 * d1) / (tp.y * tp.y);

            red_add_v2(&g_wsp[k * 128], w, w * (el + pl));
        } else {
            nsum = b; ncnt = 1.0f;
        }
    }

    // block-reduce noise, scatter to 32 padded slots
    __shared__ float nred[2][8];
    {
        float ws = warp_sum(nsum), wc = warp_sum(ncnt);
        int wid = t >> 5, lid = t & 31;
        if (lid == 0) { nred[0][wid] = ws; nred[1][wid] = wc; }
        __syncthreads();
        if (wid == 0) {
            float vs = (lid < 8) ? nred[0][lid] : 0.0f;
            float vc = (lid < 8) ? nred[1][lid] : 0.0f;
            vs = warp_sum(vs); vc = warp_sum(vc);
            if (lid == 0 && (vs != 0.0f || vc != 0.0f)) {
                int s = (blockIdx.x & 31) * 256;
                atomicAdd(&g_nacc[s], vs);
                atomicAdd(&g_nacc[s + 1], vc);
            }
        }
    }

    // finisher block
    __shared__ int sLast;
    if (t == 0) {
        __threadfence();
        unsigned old = atomicAdd(&g_done1, 1u);
        sLast = (old == gridDim.x - 1) ? 1 : 0;
    }
    __syncthreads();
    if (!sLast) return;
    if (t == 0) __threadfence();
    __syncthreads();

    // --- cluster table build ---
    float minb = 0.0f, pay = 0.0f, nobj = 0.0f, qs = 0.0f;
    if (t < KC) {
        unsigned long long key = g_key[t * 128];
        float2 wsp = g_wsp[t * 128];
        float Bx = 0.f, By = 0.f, Bz = 0.f, Bw = 0.f, q = 0.f;
        if (key != 0ull) {
            unsigned idx = 0xFFFFFFFFu - (unsigned)(key & 0xFFFFFFFFull);
            float b = clip_beta(pbeta[idx]);
            float a = atanhf(b);
            q = (a * a + Q_MIN) * ttime[idx];
            float ax = cc[3 * idx], ay = cc[3 * idx + 1], az = cc[3 * idx + 2];
            Bx = -2.0f * ax; By = -2.0f * ay; Bz = -2.0f * az;
            Bw = ax * ax + ay * ay + az * az;
            nobj = 1.0f;
            minb = 1.0f - b;
            qs = q;
            pay = wsp.y / (wsp.x + 1e-9f);
        }
        g_B4[t] = make_float4(Bx, By, Bz, Bw);
        g_q[t] = q;
        g_key[t * 128] = 0ull;
        g_wsp[t * 128] = make_float2(0.0f, 0.0f);
    }
    // noise slot aggregation + reset
    if (t < 32) {
        float vs = g_nacc[t * 256];
        float vc = g_nacc[t * 256 + 1];
        g_nacc[t * 256] = 0.0f;
        g_nacc[t * 256 + 1] = 0.0f;
        vs = warp_sum(vs); vc = warp_sum(vc);
        if (t == 0) { g_s[4] = vs; g_s[5] = vc; g_done1 = 0u; }
    }
    // minb / pay / nobj / qsum reduce
    {
        __shared__ float red[4][8];
        float wm = warp_sum(minb), wp = warp_sum(pay), wn = warp_sum(nobj), wq = warp_sum(qs);
        int wid = t >> 5, lid = t & 31;
        if (lid == 0) { red[0][wid] = wm; red[1][wid] = wp; red[2][wid] = wn; red[3][wid] = wq; }
        __syncthreads();
        if (wid == 0) {
            float vm = (lid < 8) ? red[0][lid] : 0.0f;
            float vp = (lid < 8) ? red[1][lid] : 0.0f;
            float vn = (lid < 8) ? red[2][lid] : 0.0f;
            float vq = (lid < 8) ? red[3][lid] : 0.0f;
            vm = warp_sum(vm); vp = warp_sum(vp); vn = warp_sum(vn); vq = warp_sum(vq);
            if (lid == 0) { g_s[2] = vm; g_s[3] = vp; g_s[6] = vn; g_qsum = vq; }
        }
    }
    __syncthreads();

    // --- exclusive prefix scan over 512 cell counts (Hillis-Steele, 2 elems/thread) ---
    {
        __shared__ int scn[NCELL];
        int c0 = g_ccnt[t], c1 = g_ccnt[t + 256];
        scn[t] = c0; scn[t + 256] = c1;
        __syncthreads();
        for (int off = 1; off < NCELL; off <<= 1) {
            int v0 = scn[t]       + ((t       >= off) ? scn[t - off]       : 0);
            int v1 = scn[t + 256] + ((t + 256 >= off) ? scn[t + 256 - off] : 0);
            __syncthreads();
            scn[t] = v0; scn[t + 256] = v1;
            __syncthreads();
        }
        g_cbase[t] = scn[t] - c0;
        g_cbase[t + 256] = scn[t + 256] - c1;
        g_ccnt[t] = 0; g_ccnt[t + 256] = 0;   // reset for next replay
    }
}

// ---------------- scatter: build sorted order ----------------
__global__ void __launch_bounds__(TPB1) k_scatter(int n)
{
    int i = blockIdx.x * TPB1 + threadIdx.x;
    if (i < n) {
        unsigned v = g_prank[i];
        int c = (int)(v >> 23);
        int r = (int)(v & 0x7FFFFFu);
        int dest = g_cbase[c] + r;
        if (dest < CAP) g_order[dest] = i;
    }
}

// ---------------- pass 2: sorted points + block-level cluster culling ----------------
__global__ void __launch_bounds__(TPB3) k_main(const float* __restrict__ pbeta,
                                               const float* __restrict__ cc,
                                               const float* __restrict__ ttime,
                                               const int*   __restrict__ tidx,
                                               int n, float* __restrict__ out)
{
    __shared__ float4 sLB[KC];
    __shared__ float  sLQ[KC];
    __shared__ int    sNl;
    __shared__ float  sQl;
    __shared__ float  sCx, sCy, sCz, sR;
    __shared__ float  red[16];
    __shared__ int    sLast;

    int t = threadIdx.x;
    int slot = blockIdx.x * TPB3 + t;

    float x0 = 0.f, x1 = 0.f, x2 = 0.f, q = 0.f; int km = -1;
    bool valid = (slot < n);
    if (valid) {
        int j = g_order[slot];
        x0 = cc[3 * j]; x1 = cc[3 * j + 1]; x2 = cc[3 * j + 2];
        float b = clip_beta(pbeta[j]); float a = atanhf(b);
        q = (a * a + Q_MIN) * ttime[j];
        km = tidx[j];
    }
    float ci = fmaf(x2, x2, fmaf(x1, x1, fmaf(x0, x0, 1e-9f)));

    int wid = t >> 5, lid = t & 31;

    // --- block bounding sphere: center = mean of valid points ---
    {
        float vc = valid ? 1.0f : 0.0f;
        float wx = warp_sum(valid ? x0 : 0.0f);
        float wy = warp_sum(valid ? x1 : 0.0f);
        float wz = warp_sum(valid ? x2 : 0.0f);
        float wc = warp_sum(vc);
        if (lid == 0) { red[wid] = wx; red[8 + wid] = wy; }
        __syncthreads();
        __shared__ float red2[16];
        if (lid == 0) { red2[wid] = wz; red2[8 + wid] = wc; }
        __syncthreads();
        if (t == 0) {
            float sx = 0, sy = 0, sz = 0, sc = 0;
            #pragma unroll
            for (int w = 0; w < 8; w++) { sx += red[w]; sy += red[8 + w]; sz += red2[w]; sc += red2[8 + w]; }
            float inv = 1.0f / fmaxf(sc, 1.0f);
            sCx = sx * inv; sCy = sy * inv; sCz = sz * inv;
            sNl = 0; sQl = 0.0f;
        }
        __syncthreads();
    }
    // radius
    {
        float dx = x0 - sCx, dy = x1 - sCy, dz = x2 - sCz;
        float d2 = valid ? fmaf(dx, dx, fmaf(dy, dy, dz * dz)) : 0.0f;
        float wm = warp_max(d2);
        if (lid == 0) red[wid] = wm;
        __syncthreads();
        if (t == 0) {
            float m = 0.0f;
            #pragma unroll
            for (int w = 0; w < 8; w++) m = fmaxf(m, red[w]);
            sR = fsqrt_ap(m) * 1.001f + 1e-3f;
        }
        __syncthreads();
    }

    // --- cluster culling: keep clusters within (1 + r) of block center ---
    if (t < KC) {
        float4 B = g_B4[t];
        float qk = g_q[t];
        if (qk != 0.0f) {
            float ax = -0.5f * B.x, ay = -0.5f * B.y, az = -0.5f * B.z;
            float dx = sCx - ax, dy = sCy - ay, dz = sCz - az;
            float d2c = fmaf(dx, dx, fmaf(dy, dy, dz * dz));
            float R = 1.0f + sR;
            if (d2c < R * R) {
                int p = atomicAdd(&sNl, 1);
                sLB[p] = B; sLQ[p] = qk;
                atomicAdd(&sQl, qk);
            }
        }
    }
    __syncthreads();
    int nl = sNl;
    float Qlive = sQl;

    // --- hinge loop over live clusters only ---
    float acc = 0.0f;
    #pragma unroll 4
    for (int k = 0; k < nl; k++) {
        float4 A = sLB[k]; float qa = sLQ[k];
        float ta = fmaf(A.x, x0, A.w);
        ta = fmaf(A.y, x1, ta);
        ta = fmaf(A.z, x2, ta);
        float da = __saturatef(ta + ci);
        acc = fmaf(qa, fsqrt_ap(da), acc);
    }

    float att = 0.0f, rep = 0.0f;
    if (valid) {
        float def = Qlive - acc;     // skipped clusters contribute exactly 0 to def
        if (km >= 0) {
            float4 A = g_B4[km]; float qm = g_q[km];
            float tm = fmaf(A.x, x0, A.w);
            tm = fmaf(A.y, x1, tm);
            tm = fmaf(A.z, x2, tm);
            float d2e = tm + ci;
            float m = fsqrt_ap(__saturatef(d2e));
            def -= qm * (1.0f - m);  // if member was culled, m==1 -> subtract 0 (consistent)
            att = (d2e - 1e-9f) * qm * q;
        }
        rep = q * def;
    }

    // block reduce (8 warps)
    __syncthreads();
    float wa = warp_sum(att), wr = warp_sum(rep);
    if (lid == 0) { red[wid] = wa; red[8 + wid] = wr; }
    __syncthreads();
    if (wid == 0) {
        float va = (lid < 8) ? red[lid]     : 0.0f;
        float vr = (lid < 8) ? red[8 + lid] : 0.0f;
        va = warp_sum(va); vr = warp_sum(vr);
        if (lid == 0) { atomicAdd(&g_s[0], va); atomicAdd(&g_s[1], vr); }
    }

    // finisher
    if (t == 0) {
        __threadfence();
        unsigned old = atomicAdd(&g_done2, 1u);
        sLast = (old == gridDim.x - 1) ? 1 : 0;
    }
    __syncthreads();
    if (sLast && t == 0) {
        __threadfence();
        volatile float* vs = g_s;
        float s0 = vs[0], s1 = vs[1], s2 = vs[2], s3 = vs[3];
        float s4 = vs[4], s5 = vs[5], s6 = vs[6];
        float nobj = fmaxf(s6, 1.0f);
        float ncnt = fmaxf(s5, 1.0f);
        out[0] = (s0 + s1) / (float)n + s2 / nobj + s4 / ncnt + s3 / nobj;
        g_s[0] = 0.0f; g_s[1] = 0.0f;
        g_done2 = 0u;
    }
}

// ---------------- launcher ----------------
// metadata order: 0 pred_beta, 1 pred_ccoords, 2 pred_energy, 3 pred_pos,
// 4 pred_time, 5 pred_id, 6 t_idx, 7 t_energy, 8 t_pos, 9 t_time, 10 t_pid, 11 rowsplits
extern "C" void kernel_launch(void* const* d_in, const int* in_sizes, int n_in,
                              void* d_out, int out_size) {
    const float* pbeta   = (const float*)d_in[0];
    const float* cc      = (const float*)d_in[1];
    const float* penergy = (const float*)d_in[2];
    const float* ppos    = (const float*)d_in[3];
    const int*   tidx    = (const int*)  d_in[6];
    const float* tenergy = (const float*)d_in[7];
    const float* tpos    = (const float*)d_in[8];
    const float* ttime   = (const float*)d_in[9];
    float* out = (float*)d_out;

    int n = in_sizes[0];
    int blocks = (n + TPB1 - 1) / TPB1;

    k_pass1<<<blocks, TPB1>>>(pbeta, tenergy, penergy, tpos, ppos, tidx, cc, ttime, n);
    k_scatter<<<blocks, TPB1>>>(n);
    k_main<<<blocks, TPB3>>>(pbeta, cc, ttime, tidx, n, out);
}

// round 17
// speedup vs baseline: 1.3027x; 1.3027x over previous
#include <cuda_runtime.h>
#include <math.h>

#define KC 192
#define Q_MIN 0.5f
#define TPB1 256
#define TPB3 256
#define GS 8
#define NCELL (GS * GS * GS)    // 512 cells over [-4,4]^3
#define NSL 4                   // binning sub-slots per cell
#define NCS (NCELL * NSL)       // 2048 (cell,slot) counters
#define CAP 151552

// ---------------- device scratch (no allocations allowed) ----------------
__device__ unsigned long long g_key[KC * 128];   // 1024B-strided per-cluster argmax
__device__ float2 g_wsp[KC * 128];               // {wsum, w*(el+pl)}
__device__ float g_nacc[32 * 256];

// scalar cluster table
__device__ float4 g_B4[KC];    // {Bx, By, Bz, Bw}  (B = -2a, Bw = |a|^2)
__device__ float  g_q[KC];

// counting sort: padded (cell,slot) counters (128B stride), bases, ranks, sorted SoA
__device__ int g_ccnt[NCS * 32];        // stride 32 ints = 128B
__device__ int g_cbase[NCS];
__device__ unsigned g_prank[CAP];       // (cs << 21) | rank
__device__ float4 g_sx[CAP];            // sorted {x0,x1,x2,q}
__device__ int    g_skm[CAP];           // sorted member index

// 0 att, 1 rep, 2 minb, 3 pay, 4 noise_sum, 5 noise_cnt, 6 nobj
__device__ float g_s[8];
__device__ unsigned g_done1, g_done2;

// ---------------- helpers ----------------
__device__ __forceinline__ float warp_sum(float v) {
    #pragma unroll
    for (int o = 16; o > 0; o >>= 1) v += __shfl_down_sync(0xFFFFFFFFu, v, o);
    return v;
}
__device__ __forceinline__ float warp_max(float v) {
    #pragma unroll
    for (int o = 16; o > 0; o >>= 1) v = fmaxf(v, __shfl_down_sync(0xFFFFFFFFu, v, o));
    return v;
}
__device__ __forceinline__ float clip_beta(float b) {
    return fminf(fmaxf(b, 1e-4f), 1.0f - 1e-4f);
}
__device__ __forceinline__ float fsqrt_ap(float x) {
    float r; asm("sqrt.approx.f32 %0, %1;" : "=f"(r) : "f"(x)); return r;
}
__device__ __forceinline__ void red_add_v2(float2* addr, float a, float b) {
    asm volatile("red.global.add.v2.f32 [%0], {%1, %2};" :: "l"(addr), "f"(a), "f"(b) : "memory");
}
__device__ __forceinline__ int cell_of(float x, float y, float z) {
    int cx = min(GS - 1, max(0, (int)floorf(x + 4.0f)));
    int cy = min(GS - 1, max(0, (int)floorf(y + 4.0f)));
    int cz = min(GS - 1, max(0, (int)floorf(z + 4.0f)));
    return cx + GS * cy + GS * GS * cz;
}

// ---------------- pass 1 ----------------
__global__ void __launch_bounds__(TPB1) k_pass1(const float* __restrict__ pbeta,
                        const float* __restrict__ tenergy,
                        const float* __restrict__ penergy,
                        const float* __restrict__ tpos,
                        const float* __restrict__ ppos,
                        const int*   __restrict__ tidx,
                        const float* __restrict__ cc,
                        const float* __restrict__ ttime,
                        int n)
{
    int t = threadIdx.x;
    int i = blockIdx.x * TPB1 + t;
    float nsum = 0.0f, ncnt = 0.0f;
    if (i < n) {
        float b = clip_beta(pbeta[i]);
        int k = tidx[i];

        // binning: padded (cell, slot) counter; slot decorrelates per-address contention
        float x0 = cc[3 * i], x1 = cc[3 * i + 1], x2 = cc[3 * i + 2];
        int cs = cell_of(x0, x1, x2) * NSL + (blockIdx.x & (NSL - 1));
        unsigned r = (unsigned)atomicAdd(&g_ccnt[cs * 32], 1);
        g_prank[i] = ((unsigned)cs << 21) | (r & 0x1FFFFFu);

        if (k >= 0) {
            float a = atanhf(b);
            float w = a * a;
            unsigned long long key =
                ((unsigned long long)__float_as_uint(b) << 32) |
                (unsigned long long)(0xFFFFFFFFu - (unsigned)i);
            atomicMax(&g_key[k * 128], key);

            float te = tenergy[i], pe = penergy[i];
            float de = te - pe;
            float el = (de * de) / (te * te);

            float2 tp = ((const float2*)tpos)[i];
            float2 pp = ((const float2*)ppos)[i];
            float d0 = tp.x - pp.x, d1 = tp.y - pp.y;
            float pl = (d0 * d0) / (tp.x * tp.x) + (d1 * d1) / (tp.y * tp.y);

            red_add_v2(&g_wsp[k * 128], w, w * (el + pl));
        } else {
            nsum = b; ncnt = 1.0f;
        }
    }

    // block-reduce noise
    __shared__ float nred[2][8];
    {
        float ws = warp_sum(nsum), wc = warp_sum(ncnt);
        int wid = t >> 5, lid = t & 31;
        if (lid == 0) { nred[0][wid] = ws; nred[1][wid] = wc; }
        __syncthreads();
        if (wid == 0) {
            float vs = (lid < 8) ? nred[0][lid] : 0.0f;
            float vc = (lid < 8) ? nred[1][lid] : 0.0f;
            vs = warp_sum(vs); vc = warp_sum(vc);
            if (lid == 0 && (vs != 0.0f || vc != 0.0f)) {
                int s = (blockIdx.x & 31) * 256;
                atomicAdd(&g_nacc[s], vs);
                atomicAdd(&g_nacc[s + 1], vc);
            }
        }
    }

    // finisher
    __shared__ int sLast;
    if (t == 0) {
        __threadfence();
        unsigned old = atomicAdd(&g_done1, 1u);
        sLast = (old == gridDim.x - 1) ? 1 : 0;
    }
    __syncthreads();
    if (!sLast) return;
    if (t == 0) __threadfence();
    __syncthreads();

    // cluster table
    float minb = 0.0f, pay = 0.0f, nobj = 0.0f, qs = 0.0f;
    if (t < KC) {
        unsigned long long key = g_key[t * 128];
        float2 wsp = g_wsp[t * 128];
        float Bx = 0.f, By = 0.f, Bz = 0.f, Bw = 0.f, q = 0.f;
        if (key != 0ull) {
            unsigned idx = 0xFFFFFFFFu - (unsigned)(key & 0xFFFFFFFFull);
            float b = clip_beta(pbeta[idx]);
            float a = atanhf(b);
            q = (a * a + Q_MIN) * ttime[idx];
            float ax = cc[3 * idx], ay = cc[3 * idx + 1], az = cc[3 * idx + 2];
            Bx = -2.0f * ax; By = -2.0f * ay; Bz = -2.0f * az;
            Bw = ax * ax + ay * ay + az * az;
            nobj = 1.0f;
            minb = 1.0f - b;
            qs = q;
            pay = wsp.y / (wsp.x + 1e-9f);
        }
        g_B4[t] = make_float4(Bx, By, Bz, Bw);
        g_q[t] = q;
        g_key[t * 128] = 0ull;
        g_wsp[t * 128] = make_float2(0.0f, 0.0f);
    }
    if (t < 32) {
        float vs = g_nacc[t * 256];
        float vc = g_nacc[t * 256 + 1];
        g_nacc[t * 256] = 0.0f;
        g_nacc[t * 256 + 1] = 0.0f;
        vs = warp_sum(vs); vc = warp_sum(vc);
        if (t == 0) { g_s[4] = vs; g_s[5] = vc; g_done1 = 0u; }
    }
    {
        __shared__ float red[3][8];
        float wm = warp_sum(minb), wp = warp_sum(pay), wn = warp_sum(nobj);
        warp_sum(qs); // qsum folded implicitly below via g_q; keep reductions minimal
        int wid = t >> 5, lid = t & 31;
        if (lid == 0) { red[0][wid] = wm; red[1][wid] = wp; red[2][wid] = wn; }
        __syncthreads();
        if (wid == 0) {
            float vm = (lid < 8) ? red[0][lid] : 0.0f;
            float vp = (lid < 8) ? red[1][lid] : 0.0f;
            float vn = (lid < 8) ? red[2][lid] : 0.0f;
            vm = warp_sum(vm); vp = warp_sum(vp); vn = warp_sum(vn);
            if (lid == 0) { g_s[2] = vm; g_s[3] = vp; g_s[6] = vn; }
        }
    }
    __syncthreads();

    // exclusive scan over 2048 padded (cell,slot) counters: 256 threads x 8 seq
    {
        __shared__ int lsum[256];
        int v[8]; int s = 0;
        #pragma unroll
        for (int j = 0; j < 8; j++) {
            int cs = t * 8 + j;
            v[j] = g_ccnt[cs * 32];
            g_ccnt[cs * 32] = 0;        // reset for next replay
            s += v[j];
        }
        lsum[t] = s;
        __syncthreads();
        for (int off = 1; off < 256; off <<= 1) {
            int x = lsum[t] + ((t >= off) ? lsum[t - off] : 0);
            __syncthreads();
            lsum[t] = x;
            __syncthreads();
        }
        int base = (t > 0) ? lsum[t - 1] : 0;
        #pragma unroll
        for (int j = 0; j < 8; j++) {
            g_cbase[t * 8 + j] = base;
            base += v[j];
        }
    }
}

// ---------------- scatter: materialize sorted SoA ----------------
__global__ void __launch_bounds__(TPB1) k_scatter(const float* __restrict__ pbeta,
                                                  const float* __restrict__ cc,
                                                  const float* __restrict__ ttime,
                                                  const int*   __restrict__ tidx,
                                                  int n)
{
    int i = blockIdx.x * TPB1 + threadIdx.x;
    if (i >= n) return;
    unsigned v = g_prank[i];
    int cs = (int)(v >> 21);
    int r  = (int)(v & 0x1FFFFFu);
    int dest = g_cbase[cs] + r;
    float x0 = cc[3 * i], x1 = cc[3 * i + 1], x2 = cc[3 * i + 2];
    float b = clip_beta(pbeta[i]); float a = atanhf(b);
    float q = (a * a + Q_MIN) * ttime[i];
    g_sx[dest] = make_float4(x0, x1, x2, q);
    g_skm[dest] = tidx[i];
}

// ---------------- pass 2: sorted coalesced points + block-level cluster culling ----------------
__global__ void __launch_bounds__(TPB3) k_main(int n, float* __restrict__ out)
{
    __shared__ float4 sLB[KC];
    __shared__ float  sLQ[KC];
    __shared__ int    sNl;
    __shared__ float  sQl;
    __shared__ float  sCx, sCy, sCz, sR;
    __shared__ float  red[16];
    __shared__ float  red2[16];
    __shared__ int    sLast;

    int t = threadIdx.x;
    int slot = blockIdx.x * TPB3 + t;
    int wid = t >> 5, lid = t & 31;

    float x0 = 0.f, x1 = 0.f, x2 = 0.f, q = 0.f; int km = -1;
    bool valid = (slot < n);
    if (valid) {
        float4 P = g_sx[slot];         // coalesced
        x0 = P.x; x1 = P.y; x2 = P.z; q = P.w;
        km = g_skm[slot];
    }
    float ci = fmaf(x2, x2, fmaf(x1, x1, fmaf(x0, x0, 1e-9f)));

    // bounding sphere: center = mean, radius = max dist
    {
        float wx = warp_sum(valid ? x0 : 0.0f);
        float wy = warp_sum(valid ? x1 : 0.0f);
        if (lid == 0) { red[wid] = wx; red[8 + wid] = wy; }
        float wz = warp_sum(valid ? x2 : 0.0f);
        float wc = warp_sum(valid ? 1.0f : 0.0f);
        if (lid == 0) { red2[wid] = wz; red2[8 + wid] = wc; }
        __syncthreads();
        if (t == 0) {
            float sx = 0, sy = 0, sz = 0, sc = 0;
            #pragma unroll
            for (int w = 0; w < 8; w++) { sx += red[w]; sy += red[8 + w]; sz += red2[w]; sc += red2[8 + w]; }
            float inv = 1.0f / fmaxf(sc, 1.0f);
            sCx = sx * inv; sCy = sy * inv; sCz = sz * inv;
            sNl = 0; sQl = 0.0f;
        }
        __syncthreads();
        float dx = x0 - sCx, dy = x1 - sCy, dz = x2 - sCz;
        float d2 = valid ? fmaf(dx, dx, fmaf(dy, dy, dz * dz)) : 0.0f;
        float wm = warp_max(d2);
        if (lid == 0) red[wid] = wm;
        __syncthreads();
        if (t == 0) {
            float m = 0.0f;
            #pragma unroll
            for (int w = 0; w < 8; w++) m = fmaxf(m, red[w]);
            sR = fsqrt_ap(m) * 1.001f + 1e-3f;
        }
        __syncthreads();
    }

    // cull: keep clusters within (1 + r) of center; culled ones contribute exactly 0
    if (t < KC) {
        float4 B = g_B4[t];
        float qk = g_q[t];
        if (qk != 0.0f) {
            float ax = -0.5f * B.x, ay = -0.5f * B.y, az = -0.5f * B.z;
            float dx = sCx - ax, dy = sCy - ay, dz = sCz - az;
            float d2c = fmaf(dx, dx, fmaf(dy, dy, dz * dz));
            float R = 1.0f + sR;
            if (d2c < R * R) {
                int p = atomicAdd(&sNl, 1);
                sLB[p] = B; sLQ[p] = qk;
                atomicAdd(&sQl, qk);
            }
        }
    }
    __syncthreads();
    int nl = sNl;
    float Qlive = sQl;

    float acc = 0.0f;
    #pragma unroll 4
    for (int k = 0; k < nl; k++) {
        float4 A = sLB[k]; float qa = sLQ[k];
        float ta = fmaf(A.x, x0, A.w);
        ta = fmaf(A.y, x1, ta);
        ta = fmaf(A.z, x2, ta);
        float da = __saturatef(ta + ci);
        acc = fmaf(qa, fsqrt_ap(da), acc);
    }

    float att = 0.0f, rep = 0.0f;
    if (valid) {
        float def = Qlive - acc;
        if (km >= 0) {
            float4 A = g_B4[km]; float qm = g_q[km];
            float tm = fmaf(A.x, x0, A.w);
            tm = fmaf(A.y, x1, tm);
            tm = fmaf(A.z, x2, tm);
            float d2e = tm + ci;
            float m = fsqrt_ap(__saturatef(d2e));
            def -= qm * (1.0f - m);   // if member culled, m==1 -> consistent 0
            att = (d2e - 1e-9f) * qm * q;
        }
        rep = q * def;
    }

    __syncthreads();
    float wa = warp_sum(att), wr = warp_sum(rep);
    if (lid == 0) { red[wid] = wa; red[8 + wid] = wr; }
    __syncthreads();
    if (wid == 0) {
        float va = (lid < 8) ? red[lid]     : 0.0f;
        float vr = (lid < 8) ? red[8 + lid] : 0.0f;
        va = warp_sum(va); vr = warp_sum(vr);
        if (lid == 0) { atomicAdd(&g_s[0], va); atomicAdd(&g_s[1], vr); }
    }

    if (t == 0) {
        __threadfence();
        unsigned old = atomicAdd(&g_done2, 1u);
        sLast = (old == gridDim.x - 1) ? 1 : 0;
    }
    __syncthreads();
    if (sLast && t == 0) {
        __threadfence();
        volatile float* vs = g_s;
        float s0 = vs[0], s1 = vs[1], s2 = vs[2], s3 = vs[3];
        float s4 = vs[4], s5 = vs[5], s6 = vs[6];
        float nobj = fmaxf(s6, 1.0f);
        float ncnt = fmaxf(s5, 1.0f);
        out[0] = (s0 + s1) / (float)n + s2 / nobj + s4 / ncnt + s3 / nobj;
        g_s[0] = 0.0f; g_s[1] = 0.0f;
        g_done2 = 0u;
    }
}

// ---------------- launcher ----------------
extern "C" void kernel_launch(void* const* d_in, const int* in_sizes, int n_in,
                              void* d_out, int out_size) {
    const float* pbeta   = (const float*)d_in[0];
    const float* cc      = (const float*)d_in[1];
    const float* penergy = (const float*)d_in[2];
    const float* ppos    = (const float*)d_in[3];
    const int*   tidx    = (const int*)  d_in[6];
    const float* tenergy = (const float*)d_in[7];
    const float* tpos    = (const float*)d_in[8];
    const float* ttime   = (const float*)d_in[9];
    float* out = (float*)d_out;

    int n = in_sizes[0];
    int blocks = (n + TPB1 - 1) / TPB1;

    k_pass1<<<blocks, TPB1>>>(pbeta, tenergy, penergy, tpos, ppos, tidx, cc, ttime, n);
    k_scatter<<<blocks, TPB1>>>(pbeta, cc, ttime, tidx, n);
    k_main<<<blocks, TPB3>>>(n, out);
}